// round 6
// baseline (speedup 1.0000x reference)
#include <cuda_runtime.h>

// DRNN: two stacked SimpleRNN(tanh), persistent per-CTA kernel, round 3.
// B=512 rows, T=512 steps, D=64, H=100.
// 128 CTAs x 4 rows; 320 threads = 10 warps:
//   L1 warps = wids {0,1,4,5,9} (step i), L2 warps = {2,3,6,7,8} (step i-1).
//   (Set chosen so the two 2-warp SMSPs carry pure L2 -> balanced FMA load.)
// Each lane owns TWO adjacent units (j0=li*20+2m, j1=j0+1) and one k-third
// (t = lane/10). Each activation LDS.128 feeds 4 FFMA2 (2 units x 2 pairs),
// halving shared-memory traffic vs 1-unit-per-lane. Thirds combined with two
// shfl_down. Weights in registers (<=72 u64), fma.rn.f32x2 packs 2 MACs.

#define TT   512
#define BB   512
#define DD   64
#define HH   100
#define ROWS 4
#define XS   72    // padded x row stride
#define HS   108   // padded h row stride
#define NXI  6     // ceil(16 x-quads / 3)
#define NHI  9     // ceil(25 h-quads / 3)
#define NTHR 320
#define M1SET 0x233u   // wids {0,1,4,5,9} -> layer 1

__device__ __forceinline__ void ffma2(unsigned long long &acc,
                                      unsigned long long a,
                                      unsigned long long b) {
    asm("fma.rn.f32x2 %0, %1, %2, %0;" : "+l"(acc) : "l"(a), "l"(b));
}

__device__ __forceinline__ unsigned long long pack2(float lo, float hi) {
    unsigned long long r;
    asm("mov.b64 %0, {%1, %2};" : "=l"(r) : "f"(lo), "f"(hi));
    return r;
}

__device__ __forceinline__ float hsum2(unsigned long long v) {
    float lo, hi;
    asm("mov.b64 {%0, %1}, %2;" : "=f"(lo), "=f"(hi) : "l"(v));
    return lo + hi;
}

__device__ __forceinline__ ulonglong2 lds128(const float* p) {
    return *reinterpret_cast<const ulonglong2*>(p);
}

// Accurate tanh via exp (immune to fast-math tanhf substitution).
__device__ __forceinline__ float tanh_f(float x) {
    float ax = fabsf(x);
    float e  = __expf(-2.0f * ax);
    float r  = (1.0f - e) / (1.0f + e);
    return copysignf(r, x);
}

// Accumulate NQ quad-iters over 4 rows x 2 units.
// acc[0..3] = unit0 rows, acc[4..7] = unit1 rows.
// Weight layout: w[WOFF + 4*it + {0,1,2,3}] = {u0_lo, u0_hi, u1_lo, u1_hi}.
template<int NQ, int WOFF, int RS>
__device__ __forceinline__ void accum8(unsigned long long (&acc)[8],
                                       const float* base,
                                       const unsigned long long (&w)[72])
{
    #pragma unroll
    for (int it = 0; it < NQ; ++it) {
        ulonglong2 v0 = lds128(base + 0*RS + 12*it);
        ulonglong2 v1 = lds128(base + 1*RS + 12*it);
        ulonglong2 v2 = lds128(base + 2*RS + 12*it);
        ulonglong2 v3 = lds128(base + 3*RS + 12*it);
        unsigned long long wA0 = w[WOFF + 4*it + 0];
        unsigned long long wB0 = w[WOFF + 4*it + 1];
        unsigned long long wA1 = w[WOFF + 4*it + 2];
        unsigned long long wB1 = w[WOFF + 4*it + 3];
        ffma2(acc[0], v0.x, wA0); ffma2(acc[4], v0.x, wA1);
        ffma2(acc[1], v1.x, wA0); ffma2(acc[5], v1.x, wA1);
        ffma2(acc[2], v2.x, wA0); ffma2(acc[6], v2.x, wA1);
        ffma2(acc[3], v3.x, wA0); ffma2(acc[7], v3.x, wA1);
        ffma2(acc[0], v0.y, wB0); ffma2(acc[4], v0.y, wB1);
        ffma2(acc[1], v1.y, wB0); ffma2(acc[5], v1.y, wB1);
        ffma2(acc[2], v2.y, wB0); ffma2(acc[6], v2.y, wB1);
        ffma2(acc[3], v3.y, wB0); ffma2(acc[7], v3.y, wB1);
    }
}

__device__ __forceinline__ float combine3(float p) {
    float a = __shfl_down_sync(0xffffffffu, p, 10);
    float b = __shfl_down_sync(0xffffffffu, p, 20);
    return p + a + b;          // valid on lanes 0-9
}

__global__ __launch_bounds__(NTHR, 1)
void drnn_kernel(const float* __restrict__ X,
                 const float* __restrict__ W1x, const float* __restrict__ W1h,
                 const float* __restrict__ B1,
                 const float* __restrict__ W2x, const float* __restrict__ W2h,
                 const float* __restrict__ B2,
                 const float* __restrict__ Wo,  const float* __restrict__ Bo,
                 float* __restrict__ out)
{
    __shared__ __align__(16) float sX [2][ROWS][XS];
    __shared__ __align__(16) float sH1[2][ROWS][HS];
    __shared__ __align__(16) float sH2[2][ROWS][HS];

    const int tid  = threadIdx.x;
    const int wid  = tid >> 5;
    const int lane = tid & 31;
    const int g    = ((M1SET >> wid) & 1u) ? 0 : 1;        // 0: L1, 1: L2
    const unsigned gm = g ? (~M1SET & 0x3FFu) : M1SET;
    const int li   = __popc(gm & ((1u << wid) - 1u));      // 0..4 in group
    const int t    = lane / 10;                            // k-third (3 = idle)
    const int m    = lane % 10;
    const int tt   = (t > 2) ? 2 : t;
    const int j0   = li * 20 + 2 * m;                      // units j0, j0+1
    const int r0   = blockIdx.x * ROWS;

    // Weight regs. L1 layout: x-part [0..23], h-part [24..59].
    //              L2 layout: h1-part [0..35], h2-part [36..71].
    unsigned long long w[72];
    #pragma unroll
    for (int n = 0; n < 72; ++n) w[n] = 0ull;
    float bj0 = 0.f, bj1 = 0.f;

    if (t < 3) {
        if (g == 0) {
            #pragma unroll
            for (int u = 0; u < 2; ++u) {
                const int j = j0 + u;
                #pragma unroll
                for (int qi = 0; qi < NXI; ++qi) {
                    int q = 3*qi + tt;
                    if (q < 16) {
                        int k = 4*q;
                        w[4*qi + 2*u    ] = pack2(W1x[(k  )*HH + j], W1x[(k+1)*HH + j]);
                        w[4*qi + 2*u + 1] = pack2(W1x[(k+2)*HH + j], W1x[(k+3)*HH + j]);
                    }
                }
                #pragma unroll
                for (int qi = 0; qi < NHI; ++qi) {
                    int q = 3*qi + tt;
                    if (q < 25) {
                        int k = 4*q;
                        w[24 + 4*qi + 2*u    ] = pack2(W1h[(k  )*HH + j], W1h[(k+1)*HH + j]);
                        w[24 + 4*qi + 2*u + 1] = pack2(W1h[(k+2)*HH + j], W1h[(k+3)*HH + j]);
                    }
                }
            }
            bj0 = B1[j0]; bj1 = B1[j0 + 1];
        } else {
            #pragma unroll
            for (int u = 0; u < 2; ++u) {
                const int j = j0 + u;
                #pragma unroll
                for (int qi = 0; qi < NHI; ++qi) {
                    int q = 3*qi + tt;
                    if (q < 25) {
                        int k = 4*q;
                        w[4*qi + 2*u    ] = pack2(W2x[(k  )*HH + j], W2x[(k+1)*HH + j]);
                        w[4*qi + 2*u + 1] = pack2(W2x[(k+2)*HH + j], W2x[(k+3)*HH + j]);
                        w[36 + 4*qi + 2*u    ] = pack2(W2h[(k  )*HH + j], W2h[(k+1)*HH + j]);
                        w[36 + 4*qi + 2*u + 1] = pack2(W2h[(k+2)*HH + j], W2h[(k+3)*HH + j]);
                    }
                }
            }
            bj0 = B2[j0]; bj1 = B2[j0 + 1];
        }
    }

    // Zero all shared buffers (states h_{-1}=0; pads must be finite-0).
    {
        float* zx = &sX[0][0][0];
        for (int idx = tid; idx < 2*ROWS*XS; idx += NTHR) zx[idx] = 0.f;
        float* z1 = &sH1[0][0][0];
        for (int idx = tid; idx < 2*ROWS*HS; idx += NTHR) z1[idx] = 0.f;
        float* z2 = &sH2[0][0][0];
        for (int idx = tid; idx < 2*ROWS*HS; idx += NTHR) z2[idx] = 0.f;
    }
    __syncthreads();
    // Stage x_0 (256 floats by first 256 threads).
    if (tid < 256) {
        int r = tid >> 6, d = tid & 63;
        sX[0][r][d] = X[(size_t)(r0 + r)*TT*DD + d];
    }
    __syncthreads();

    const int lti = li*32 + lane;   // 0..159 within L1 group

    for (int i = 0; i <= TT; ++i) {
        if (g == 0) {
            // Prefetch x_{i+1}: 256 floats by 160 L1 threads (some do 2).
            float xpfA = 0.f, xpfB = 0.f;
            const int iA = lti, iB = lti + 160;
            const bool doB = (lti < 96);
            const bool pf  = (i + 1 < TT);
            if (pf) {
                const float* xs = X + (size_t)r0*TT*DD + (size_t)(i+1)*DD;
                xpfA = xs[(size_t)(iA >> 6)*TT*DD + (iA & 63)];
                if (doB) xpfB = xs[(size_t)(iB >> 6)*TT*DD + (iB & 63)];
            }
            if (i < TT) {
                const int pc = i & 1, pp = pc ^ 1;
                unsigned long long acc[8];
                #pragma unroll
                for (int n = 0; n < 8; ++n) acc[n] = 0ull;
                accum8<NXI, 0,  XS>(acc, &sX [pc][0][0] + 4*tt, w);
                accum8<NHI, 24, HS>(acc, &sH1[pp][0][0] + 4*tt, w);
                float s[8];
                #pragma unroll
                for (int n = 0; n < 8; ++n) s[n] = combine3(hsum2(acc[n]));
                if (t == 0) {
                    #pragma unroll
                    for (int r = 0; r < ROWS; ++r) {
                        float2 hv;
                        hv.x = tanh_f(s[r]     + bj0);
                        hv.y = tanh_f(s[4 + r] + bj1);
                        *reinterpret_cast<float2*>(&sH1[pc][r][j0]) = hv;
                    }
                }
            }
            if (pf) {
                const int pn = (i + 1) & 1;
                sX[pn][iA >> 6][iA & 63] = xpfA;
                if (doB) sX[pn][iB >> 6][iB & 63] = xpfB;
            }
        } else {
            if (i >= 1) {
                const int s0i = i - 1;
                const int pc = s0i & 1, pp = pc ^ 1;
                unsigned long long acc[8];
                #pragma unroll
                for (int n = 0; n < 8; ++n) acc[n] = 0ull;
                accum8<NHI, 0,  HS>(acc, &sH1[pc][0][0] + 4*tt, w);
                accum8<NHI, 36, HS>(acc, &sH2[pp][0][0] + 4*tt, w);
                float s[8];
                #pragma unroll
                for (int n = 0; n < 8; ++n) s[n] = combine3(hsum2(acc[n]));
                if (t == 0) {
                    #pragma unroll
                    for (int r = 0; r < ROWS; ++r) {
                        float2 hv;
                        hv.x = tanh_f(s[r]     + bj0);
                        hv.y = tanh_f(s[4 + r] + bj1);
                        *reinterpret_cast<float2*>(&sH2[pc][r][j0]) = hv;
                    }
                }
            }
        }
        __syncthreads();
    }

    // Final states live at parity (TT-1)&1 == 1.
    float* outVec = out;                      // [512]
    float* outH1  = out + BB;                 // [512,100]
    float* outH2  = out + BB + BB*HH;         // [512,100]

    for (int idx = tid; idx < ROWS*HH; idx += NTHR) {
        int r = idx / HH, jj = idx % HH;
        outH1[(size_t)(r0 + r)*HH + jj] = sH1[1][r][jj];
        outH2[(size_t)(r0 + r)*HH + jj] = sH2[1][r][jj];
    }

    // Output head: out[r] = h2_T[r] . Wo + bo  (warp 0 does all 4 rows)
    if (tid < 32) {
        #pragma unroll
        for (int r = 0; r < ROWS; ++r) {
            float v = 0.f;
            #pragma unroll
            for (int mm = 0; mm < 4; ++mm) {
                int jj = mm*32 + tid;
                if (jj < HH) v += sH2[1][r][jj] * Wo[jj];
            }
            #pragma unroll
            for (int off = 16; off; off >>= 1)
                v += __shfl_down_sync(0xffffffffu, v, off);
            if (tid == 0) outVec[r0 + r] = v + Bo[0];
        }
    }
}

extern "C" void kernel_launch(void* const* d_in, const int* in_sizes, int n_in,
                              void* d_out, int out_size) {
    (void)in_sizes; (void)n_in; (void)out_size;
    const float* X   = (const float*)d_in[0];
    const float* W1x = (const float*)d_in[1];
    const float* W1h = (const float*)d_in[2];
    const float* B1  = (const float*)d_in[3];
    const float* W2x = (const float*)d_in[4];
    const float* W2h = (const float*)d_in[5];
    const float* B2  = (const float*)d_in[6];
    const float* Wo  = (const float*)d_in[7];
    const float* Bo  = (const float*)d_in[8];
    drnn_kernel<<<BB/ROWS, NTHR>>>(X, W1x, W1h, B1, W2x, W2h, B2, Wo, Bo,
                                   (float*)d_out);
}

// round 7
// speedup vs baseline: 1.0492x; 1.0492x over previous
#include <cuda_runtime.h>

// DRNN: two stacked SimpleRNN(tanh), persistent per-CTA kernel, round 4.
// B=512 rows, T=512 steps, D=64, H=100. 128 CTAs x 4 rows, 448 threads.
// 14 warps: L1 wids {1,4,5,8,9,12,13}, L2 wids {0,2,3,6,7,10,11}
//   (placement gives per-SMSP FFMA2 loads 712/672/624/624 -> best balance).
// Each warp covers 16 units; lane = (half, unit): u = 16*wl + (lane&15),
// half = lane>>4 owns a 2-way split of the k-reduction. Combine = ONE
// shfl_down(16) + add (minimal tail). Weights in registers:
//   L1: 8 x-quads + 13 h-quads = 42 u64 (~125 regs)
//   L2: 13 + 13 h-quads       = 52 u64 (~135 regs)  [cap 146 @ 448 thr]
// fma.rn.f32x2 packs 2 MACs/instr; activations via broadcast LDS.128.

#define TT   512
#define BB   512
#define DD   64
#define HH   100
#define ROWS 4
#define XS   64     // x row stride: 16 quads exactly
#define HS   104    // h row stride: 26 quads (q25 = zero pad)
#define NTHR 448
#define L1SET 0x3332u   // wids {1,4,5,8,9,12,13}

__device__ __forceinline__ void ffma2(unsigned long long &acc,
                                      unsigned long long a,
                                      unsigned long long b) {
    asm("fma.rn.f32x2 %0, %1, %2, %0;" : "+l"(acc) : "l"(a), "l"(b));
}

__device__ __forceinline__ unsigned long long pack2(float lo, float hi) {
    unsigned long long r;
    asm("mov.b64 %0, {%1, %2};" : "=l"(r) : "f"(lo), "f"(hi));
    return r;
}

__device__ __forceinline__ float hsum2(unsigned long long v) {
    float lo, hi;
    asm("mov.b64 {%0, %1}, %2;" : "=f"(lo), "=f"(hi) : "l"(v));
    return lo + hi;
}

__device__ __forceinline__ ulonglong2 lds128(const float* p) {
    return *reinterpret_cast<const ulonglong2*>(p);
}

// Accurate tanh via exp (immune to fast-math tanhf substitution).
__device__ __forceinline__ float tanh_f(float x) {
    float ax = fabsf(x);
    float e  = __expf(-2.0f * ax);
    float r  = (1.0f - e) / (1.0f + e);
    return copysignf(r, x);
}

// acc[r] += dot(act_row_r[quads], w[WOFF..]) for 4 rows, NQ quads,
// row stride RS floats. base already offset to this lane's half.
template<int NQ, int WOFF, int RS>
__device__ __forceinline__ void accum4(unsigned long long (&acc)[4],
                                       const float* base,
                                       const unsigned long long (&w)[52])
{
    #pragma unroll
    for (int it = 0; it < NQ; ++it) {
        ulonglong2 v0 = lds128(base + 0*RS + 4*it);
        ulonglong2 v1 = lds128(base + 1*RS + 4*it);
        ulonglong2 v2 = lds128(base + 2*RS + 4*it);
        ulonglong2 v3 = lds128(base + 3*RS + 4*it);
        unsigned long long wA = w[WOFF + 2*it];
        unsigned long long wB = w[WOFF + 2*it + 1];
        ffma2(acc[0], v0.x, wA); ffma2(acc[1], v1.x, wA);
        ffma2(acc[2], v2.x, wA); ffma2(acc[3], v3.x, wA);
        ffma2(acc[0], v0.y, wB); ffma2(acc[1], v1.y, wB);
        ffma2(acc[2], v2.y, wB); ffma2(acc[3], v3.y, wB);
    }
}

__global__ __launch_bounds__(NTHR, 1)
void drnn_kernel(const float* __restrict__ X,
                 const float* __restrict__ W1x, const float* __restrict__ W1h,
                 const float* __restrict__ B1,
                 const float* __restrict__ W2x, const float* __restrict__ W2h,
                 const float* __restrict__ B2,
                 const float* __restrict__ Wo,  const float* __restrict__ Bo,
                 float* __restrict__ out)
{
    __shared__ __align__(16) float sX [2][ROWS][XS];
    __shared__ __align__(16) float sH1[2][ROWS][HS];
    __shared__ __align__(16) float sH2[2][ROWS][HS];

    const int tid  = threadIdx.x;
    const int wid  = tid >> 5;
    const int lane = tid & 31;
    const int g    = ((L1SET >> wid) & 1u) ? 0 : 1;          // 0: L1, 1: L2
    const unsigned gm = g ? (~L1SET & 0x3FFFu) : L1SET;
    const int wl   = __popc(gm & ((1u << wid) - 1u));        // 0..6 in group
    const int half = lane >> 4;                              // k-half 0/1
    const int u    = wl * 16 + (lane & 15);                  // unit 0..111
    const int uu   = (u < HH) ? u : (HH - 1);                // clamped (safe ld)
    const int r0   = blockIdx.x * ROWS;

    // Weight registers.
    // L1: [0..15] = x-quads (8), [16..41] = h1-quads (13).
    // L2: [0..25] = h1-quads (13), [26..51] = h2-quads (13).
    unsigned long long w[52];
    #pragma unroll
    for (int n = 0; n < 52; ++n) w[n] = 0ull;
    float bj;

    if (g == 0) {
        #pragma unroll
        for (int qi = 0; qi < 8; ++qi) {                     // x-part: k < 64 always
            int k = 4 * (half * 8 + qi);
            w[2*qi]   = pack2(W1x[(k  )*HH + uu], W1x[(k+1)*HH + uu]);
            w[2*qi+1] = pack2(W1x[(k+2)*HH + uu], W1x[(k+3)*HH + uu]);
        }
        #pragma unroll
        for (int qi = 0; qi < 13; ++qi) {                    // h-part, q<=25, pad->0
            int k = 4 * (half * 13 + qi);
            float a = (k   < HH) ? W1h[(k  )*HH + uu] : 0.f;
            float b = (k+1 < HH) ? W1h[(k+1)*HH + uu] : 0.f;
            float c = (k+2 < HH) ? W1h[(k+2)*HH + uu] : 0.f;
            float d = (k+3 < HH) ? W1h[(k+3)*HH + uu] : 0.f;
            w[16 + 2*qi]     = pack2(a, b);
            w[16 + 2*qi + 1] = pack2(c, d);
        }
        bj = B1[uu];
    } else {
        #pragma unroll
        for (int qi = 0; qi < 13; ++qi) {                    // W2x (acts on h1)
            int k = 4 * (half * 13 + qi);
            float a = (k   < HH) ? W2x[(k  )*HH + uu] : 0.f;
            float b = (k+1 < HH) ? W2x[(k+1)*HH + uu] : 0.f;
            float c = (k+2 < HH) ? W2x[(k+2)*HH + uu] : 0.f;
            float d = (k+3 < HH) ? W2x[(k+3)*HH + uu] : 0.f;
            w[2*qi]     = pack2(a, b);
            w[2*qi + 1] = pack2(c, d);
        }
        #pragma unroll
        for (int qi = 0; qi < 13; ++qi) {                    // W2h (acts on h2)
            int k = 4 * (half * 13 + qi);
            float a = (k   < HH) ? W2h[(k  )*HH + uu] : 0.f;
            float b = (k+1 < HH) ? W2h[(k+1)*HH + uu] : 0.f;
            float c = (k+2 < HH) ? W2h[(k+2)*HH + uu] : 0.f;
            float d = (k+3 < HH) ? W2h[(k+3)*HH + uu] : 0.f;
            w[26 + 2*qi]     = pack2(a, b);
            w[26 + 2*qi + 1] = pack2(c, d);
        }
        bj = B2[uu];
    }

    // Zero shared buffers (h_{-1}=0; pads must stay finite-0).
    {
        float* zx = &sX[0][0][0];
        for (int idx = tid; idx < 2*ROWS*XS; idx += NTHR) zx[idx] = 0.f;
        float* z1 = &sH1[0][0][0];
        for (int idx = tid; idx < 2*ROWS*HS; idx += NTHR) z1[idx] = 0.f;
        float* z2 = &sH2[0][0][0];
        for (int idx = tid; idx < 2*ROWS*HS; idx += NTHR) z2[idx] = 0.f;
    }
    __syncthreads();
    // Stage x_0.
    if (tid < 256) {
        int r = tid >> 6, d = tid & 63;
        sX[0][r][d] = X[(size_t)(r0 + r)*TT*DD + d];
    }
    __syncthreads();

    const int lti = wl*32 + lane;            // 0..223 within L1 group
    const int xofs = 4 * (half * 8);         // this lane's x half (floats)
    const int hofs = 4 * (half * 13);        // this lane's h half (floats)
    const bool wr  = (half == 0) && (u < HH);

    for (int i = 0; i <= TT; ++i) {
        if (g == 0) {
            // Prefetch x_{i+1}: 256 floats by 224 L1 lanes (first 32 do 2).
            float xpfA = 0.f, xpfB = 0.f;
            const int iA = lti, iB = lti + 224;
            const bool doB = (lti < 32);
            const bool pf  = (i + 1 < TT);
            if (pf) {
                const float* xs = X + (size_t)r0*TT*DD + (size_t)(i+1)*DD;
                xpfA = xs[(size_t)(iA >> 6)*TT*DD + (iA & 63)];
                if (doB) xpfB = xs[(size_t)(iB >> 6)*TT*DD + (iB & 63)];
            }
            if (i < TT) {
                const int pc = i & 1, pp = pc ^ 1;
                unsigned long long acc[4];
                #pragma unroll
                for (int n = 0; n < 4; ++n) acc[n] = 0ull;
                accum4<8, 0,  XS>(acc, &sX [pc][0][0] + xofs, w);
                accum4<13, 16, HS>(acc, &sH1[pp][0][0] + hofs, w);
                float p0 = hsum2(acc[0]), p1 = hsum2(acc[1]);
                float p2 = hsum2(acc[2]), p3 = hsum2(acc[3]);
                float q0 = __shfl_down_sync(0xffffffffu, p0, 16);
                float q1 = __shfl_down_sync(0xffffffffu, p1, 16);
                float q2 = __shfl_down_sync(0xffffffffu, p2, 16);
                float q3 = __shfl_down_sync(0xffffffffu, p3, 16);
                if (wr) {
                    sH1[pc][0][u] = tanh_f(p0 + q0 + bj);
                    sH1[pc][1][u] = tanh_f(p1 + q1 + bj);
                    sH1[pc][2][u] = tanh_f(p2 + q2 + bj);
                    sH1[pc][3][u] = tanh_f(p3 + q3 + bj);
                }
            }
            if (pf) {
                const int pn = (i + 1) & 1;
                sX[pn][iA >> 6][iA & 63] = xpfA;
                if (doB) sX[pn][iB >> 6][iB & 63] = xpfB;
            }
        } else {
            if (i >= 1) {
                const int s  = i - 1;
                const int pc = s & 1, pp = pc ^ 1;
                unsigned long long acc[4];
                #pragma unroll
                for (int n = 0; n < 4; ++n) acc[n] = 0ull;
                accum4<13, 0,  HS>(acc, &sH1[pc][0][0] + hofs, w);
                accum4<13, 26, HS>(acc, &sH2[pp][0][0] + hofs, w);
                float p0 = hsum2(acc[0]), p1 = hsum2(acc[1]);
                float p2 = hsum2(acc[2]), p3 = hsum2(acc[3]);
                float q0 = __shfl_down_sync(0xffffffffu, p0, 16);
                float q1 = __shfl_down_sync(0xffffffffu, p1, 16);
                float q2 = __shfl_down_sync(0xffffffffu, p2, 16);
                float q3 = __shfl_down_sync(0xffffffffu, p3, 16);
                if (wr) {
                    sH2[pc][0][u] = tanh_f(p0 + q0 + bj);
                    sH2[pc][1][u] = tanh_f(p1 + q1 + bj);
                    sH2[pc][2][u] = tanh_f(p2 + q2 + bj);
                    sH2[pc][3][u] = tanh_f(p3 + q3 + bj);
                }
            }
        }
        __syncthreads();
    }

    // Final states at parity (TT-1)&1 == 1.
    float* outVec = out;                      // [512]
    float* outH1  = out + BB;                 // [512,100]
    float* outH2  = out + BB + BB*HH;         // [512,100]

    for (int idx = tid; idx < ROWS*HH; idx += NTHR) {
        int r = idx / HH, jj = idx % HH;
        outH1[(size_t)(r0 + r)*HH + jj] = sH1[1][r][jj];
        outH2[(size_t)(r0 + r)*HH + jj] = sH2[1][r][jj];
    }

    // Output head: out[r] = h2_T[r] . Wo + bo  (warp 0 does all 4 rows)
    if (tid < 32) {
        #pragma unroll
        for (int r = 0; r < ROWS; ++r) {
            float v = 0.f;
            #pragma unroll
            for (int mm = 0; mm < 4; ++mm) {
                int jj = mm*32 + tid;
                if (jj < HH) v += sH2[1][r][jj] * Wo[jj];
            }
            #pragma unroll
            for (int off = 16; off; off >>= 1)
                v += __shfl_down_sync(0xffffffffu, v, off);
            if (tid == 0) outVec[r0 + r] = v + Bo[0];
        }
    }
}

extern "C" void kernel_launch(void* const* d_in, const int* in_sizes, int n_in,
                              void* d_out, int out_size) {
    (void)in_sizes; (void)n_in; (void)out_size;
    const float* X   = (const float*)d_in[0];
    const float* W1x = (const float*)d_in[1];
    const float* W1h = (const float*)d_in[2];
    const float* B1  = (const float*)d_in[3];
    const float* W2x = (const float*)d_in[4];
    const float* W2h = (const float*)d_in[5];
    const float* B2  = (const float*)d_in[6];
    const float* Wo  = (const float*)d_in[7];
    const float* Bo  = (const float*)d_in[8];
    drnn_kernel<<<BB/ROWS, NTHR>>>(X, W1x, W1h, B1, W2x, W2h, B2, Wo, Bo,
                                   (float*)d_out);
}

// round 8
// speedup vs baseline: 1.2802x; 1.2202x over previous
#include <cuda_runtime.h>

// DRNN: two stacked SimpleRNN(tanh), persistent per-CTA kernel, round 5.
// B=512, T=512, D=64, H=100. 128 CTAs x 4 rows, 512 threads = 16 warps.
// 4 pipeline-stage groups of 4 warps (gid = wid>>2), one warp of each group
// per SMSP (perfect FMA balance, 4 warps/SMSP):
//   G_x : xp_{i+1} = W1x.x_{i+1} + b1   (feed-forward, 32 u64 wregs + x LDG)
//   G1  : h1_i   = tanh(xp_i + W1h.h1_{i-1})          (50 u64 wregs)
//   G2a : p_{i-1} = W2x.h1_{i-1} + b2                 (50 u64 wregs)
//   G2b : h2_{i-2}= tanh(p_{i-2} + W2h.h2_{i-3})      (50 u64 wregs)
// R0's winning shape kept: 1 unit/lane, full k-column, broadcast LDS.128,
// zero shuffles. fma.rn.f32x2 packs 2 MACs/instr. tanh uses __fdividef.
// Single __syncthreads per step; parity-double-buffered smem rings.

#define TT   512
#define BB   512
#define DD   64
#define HH   100
#define ROWS 4
#define XSR  64     // x row stride (16 quads exact)
#define HSR  104    // h/xp/p row stride (25 quads exact + 16B-align pad)
#define NTHR 512

__device__ __forceinline__ void ffma2(unsigned long long &acc,
                                      unsigned long long a,
                                      unsigned long long b) {
    asm("fma.rn.f32x2 %0, %1, %2, %0;" : "+l"(acc) : "l"(a), "l"(b));
}

__device__ __forceinline__ unsigned long long pack2(float lo, float hi) {
    unsigned long long r;
    asm("mov.b64 %0, {%1, %2};" : "=l"(r) : "f"(lo), "f"(hi));
    return r;
}

__device__ __forceinline__ float hsum2(unsigned long long v) {
    float lo, hi;
    asm("mov.b64 {%0, %1}, %2;" : "=f"(lo), "=f"(hi) : "l"(v));
    return lo + hi;
}

__device__ __forceinline__ ulonglong2 lds128(const float* p) {
    return *reinterpret_cast<const ulonglong2*>(p);
}

// tanh via exp + fast divide (RCP+refine-free): ~1e-7 rel err, cheap tail.
__device__ __forceinline__ float tanh_f(float x) {
    float ax = fabsf(x);
    float e  = __expf(-2.0f * ax);
    float r  = __fdividef(1.0f - e, 1.0f + e);
    return copysignf(r, x);
}

// acc[r] += dot(act_row_r, w) over NQ quads; broadcast LDS (same addr/warp).
template<int NQ, int RS>
__device__ __forceinline__ void accum4(unsigned long long (&acc)[4],
                                       const float* base,
                                       const unsigned long long* w)
{
    #pragma unroll
    for (int it = 0; it < NQ; ++it) {
        ulonglong2 v0 = lds128(base + 0*RS + 4*it);
        ulonglong2 v1 = lds128(base + 1*RS + 4*it);
        ulonglong2 v2 = lds128(base + 2*RS + 4*it);
        ulonglong2 v3 = lds128(base + 3*RS + 4*it);
        unsigned long long wA = w[2*it];
        unsigned long long wB = w[2*it + 1];
        ffma2(acc[0], v0.x, wA); ffma2(acc[1], v1.x, wA);
        ffma2(acc[2], v2.x, wA); ffma2(acc[3], v3.x, wA);
        ffma2(acc[0], v0.y, wB); ffma2(acc[1], v1.y, wB);
        ffma2(acc[2], v2.y, wB); ffma2(acc[3], v3.y, wB);
    }
}

__global__ __launch_bounds__(NTHR, 1)
void drnn_kernel(const float* __restrict__ X,
                 const float* __restrict__ W1x, const float* __restrict__ W1h,
                 const float* __restrict__ B1,
                 const float* __restrict__ W2x, const float* __restrict__ W2h,
                 const float* __restrict__ B2,
                 const float* __restrict__ Wo,  const float* __restrict__ Bo,
                 float* __restrict__ out)
{
    __shared__ __align__(16) float sX [2][ROWS][XSR];
    __shared__ __align__(16) float sH1[2][ROWS][HSR];
    __shared__ __align__(16) float sH2[2][ROWS][HSR];
    __shared__ __align__(16) float sXP[2][ROWS][HSR];   // xp = W1x.x + b1
    __shared__ __align__(16) float sP [2][ROWS][HSR];   // p  = W2x.h1 + b2

    const int tid  = threadIdx.x;
    const int wid  = tid >> 5;
    const int lane = tid & 31;
    const int gid  = wid >> 2;                 // 0:Gx 1:G1 2:G2a 3:G2b
    const int wl   = wid & 3;                  // warp within group = SMSP id
    const int j    = wl * 32 + lane;           // unit 0..127
    const int jj   = (j < HH) ? j : (HH - 1);  // clamped for safe weight loads
    const bool act = (j < HH);
    const int r0   = blockIdx.x * ROWS;

    // Per-group weight column (register-resident, <=50 u64).
    unsigned long long w[50];
    #pragma unroll
    for (int n = 0; n < 50; ++n) w[n] = 0ull;
    float bj = 0.f;

    if (gid == 0) {
        #pragma unroll
        for (int q = 0; q < 16; ++q) {                 // W1x: 64 x-rows
            int k = 4 * q;
            w[2*q]   = pack2(W1x[(k  )*HH + jj], W1x[(k+1)*HH + jj]);
            w[2*q+1] = pack2(W1x[(k+2)*HH + jj], W1x[(k+3)*HH + jj]);
        }
        bj = B1[jj];                                   // b1 folded into xp
    } else {
        const float* Wsrc = (gid == 1) ? W1h : ((gid == 2) ? W2x : W2h);
        #pragma unroll
        for (int q = 0; q < 25; ++q) {                 // 100 h-rows exact
            int k = 4 * q;
            w[2*q]   = pack2(Wsrc[(k  )*HH + jj], Wsrc[(k+1)*HH + jj]);
            w[2*q+1] = pack2(Wsrc[(k+2)*HH + jj], Wsrc[(k+3)*HH + jj]);
        }
        if (gid == 2) bj = B2[jj];                     // b2 folded into p
    }

    // Zero state rings (h1_{-1} = h2_{-1} = h2_{-2}... = 0).
    {
        float* z1 = &sH1[0][0][0];
        for (int idx = tid; idx < 2*ROWS*HSR; idx += NTHR) z1[idx] = 0.f;
        float* z2 = &sH2[0][0][0];
        for (int idx = tid; idx < 2*ROWS*HSR; idx += NTHR) z2[idx] = 0.f;
    }
    // Stage x_0 -> sX[0], x_1 -> sX[1].
    {
        int p = tid & 255, buf = tid >> 8;             // 512 thr = 2 x 256
        int r = p >> 6, d = p & 63;
        sX[buf][r][d] = X[(size_t)(r0 + r)*TT*DD + (size_t)buf*DD + d];
    }
    __syncthreads();

    // Prologue: G_x computes xp_0 into sXP[0].
    if (gid == 0) {
        unsigned long long a[4] = {0ull, 0ull, 0ull, 0ull};
        accum4<16, XSR>(a, &sX[0][0][0], w);
        if (act) {
            #pragma unroll
            for (int r = 0; r < ROWS; ++r)
                sXP[0][r][j] = hsum2(a[r]) + bj;
        }
    }
    __syncthreads();

    for (int i = 0; i <= TT + 1; ++i) {
        const int pc = i & 1, pn = pc ^ 1;
        if (gid == 0) {
            // LDG x_{i+2} early (hidden under this step's FMA work).
            float xpfA = 0.f, xpfB = 0.f;
            const int qA = j, qB = j + 128;            // 128 lanes x 2 = 256
            const bool dl = (i + 2 < TT);
            if (dl) {
                const float* xs = X + (size_t)r0*TT*DD + (size_t)(i+2)*DD;
                xpfA = xs[(size_t)(qA >> 6)*TT*DD + (qA & 63)];
                xpfB = xs[(size_t)(qB >> 6)*TT*DD + (qB & 63)];
            }
            if (i + 1 <= TT - 1) {                     // xp_{i+1}
                unsigned long long a[4] = {0ull, 0ull, 0ull, 0ull};
                accum4<16, XSR>(a, &sX[pn][0][0], w);
                if (act) {
                    #pragma unroll
                    for (int r = 0; r < ROWS; ++r)
                        sXP[pn][r][j] = hsum2(a[r]) + bj;
                }
            }
            if (dl) {
                sX[pc][qA >> 6][qA & 63] = xpfA;
                sX[pc][qB >> 6][qB & 63] = xpfB;
            }
        } else if (gid == 1) {
            if (i <= TT - 1) {                         // h1_i
                unsigned long long a[4] = {0ull, 0ull, 0ull, 0ull};
                accum4<25, HSR>(a, &sH1[pn][0][0], w);
                if (act) {
                    #pragma unroll
                    for (int r = 0; r < ROWS; ++r)
                        sH1[pc][r][j] = tanh_f(hsum2(a[r]) + sXP[pc][r][j]);
                }
            }
        } else if (gid == 2) {
            if (i >= 1 && i <= TT) {                   // p_{i-1}
                unsigned long long a[4] = {0ull, 0ull, 0ull, 0ull};
                accum4<25, HSR>(a, &sH1[pn][0][0], w);
                if (act) {
                    #pragma unroll
                    for (int r = 0; r < ROWS; ++r)
                        sP[pn][r][j] = hsum2(a[r]) + bj;
                }
            }
        } else {
            if (i >= 2) {                              // h2_{i-2}
                unsigned long long a[4] = {0ull, 0ull, 0ull, 0ull};
                accum4<25, HSR>(a, &sH2[pn][0][0], w);
                if (act) {
                    #pragma unroll
                    for (int r = 0; r < ROWS; ++r)
                        sH2[pc][r][j] = tanh_f(hsum2(a[r]) + sP[pc][r][j]);
                }
            }
        }
        __syncthreads();
    }

    // h1_511 in sH1[1], h2_511 in sH2[1] (written at wall-step 513, pc=1).
    float* outVec = out;                      // [512]
    float* outH1  = out + BB;                 // [512,100]
    float* outH2  = out + BB + BB*HH;         // [512,100]

    for (int idx = tid; idx < ROWS*HH; idx += NTHR) {
        int r = idx / HH, u = idx % HH;
        outH1[(size_t)(r0 + r)*HH + u] = sH1[1][r][u];
        outH2[(size_t)(r0 + r)*HH + u] = sH2[1][r][u];
    }

    // Output head: out[r] = h2_T[r] . Wo + bo  (warp 0).
    if (tid < 32) {
        #pragma unroll
        for (int r = 0; r < ROWS; ++r) {
            float v = 0.f;
            #pragma unroll
            for (int mm = 0; mm < 4; ++mm) {
                int u = mm*32 + tid;
                if (u < HH) v += sH2[1][r][u] * Wo[u];
            }
            #pragma unroll
            for (int off = 16; off; off >>= 1)
                v += __shfl_down_sync(0xffffffffu, v, off);
            if (tid == 0) outVec[r0 + r] = v + Bo[0];
        }
    }
}

extern "C" void kernel_launch(void* const* d_in, const int* in_sizes, int n_in,
                              void* d_out, int out_size) {
    (void)in_sizes; (void)n_in; (void)out_size;
    const float* X   = (const float*)d_in[0];
    const float* W1x = (const float*)d_in[1];
    const float* W1h = (const float*)d_in[2];
    const float* B1  = (const float*)d_in[3];
    const float* W2x = (const float*)d_in[4];
    const float* W2h = (const float*)d_in[5];
    const float* B2  = (const float*)d_in[6];
    const float* Wo  = (const float*)d_in[7];
    const float* Bo  = (const float*)d_in[8];
    drnn_kernel<<<BB/ROWS, NTHR>>>(X, W1x, W1h, B1, W2x, W2h, B2, Wo, Bo,
                                   (float*)d_out);
}